// round 12
// baseline (speedup 1.0000x reference)
#include <cuda_runtime.h>
#include <math.h>

typedef unsigned long long ull;

#define TPB 256

// ---- shared memory float offsets (86256 B -> 2 blocks/SM @ 172.5 KB) ----
#define W1_OFF    0        // conv1 [pass(5)][c(21)][k(9)][4oc] : 3780
#define W2_OFF    3780     // conv2 [oc][q][32pad] : 2560
#define FC1P_OFF  6340     // fc1 [j1][32] (cols 0..29, pad 0) : 3840
#define FC1OH_OFF 10180    // fc1 one-hot cols [j1][8] : 960
#define FC2T_OFF  11140    // fc2 transposed [j1][84] : 10080
#define FC3_OFF   21220    // 84
#define B1_OFF    21304    // 20
#define B2P_OFF   21324    // 32
#define FB1_OFF   21356    // 120
#define FB2_OFF   21476    // 84
#define FB3_OFF   21560    // 1 (+3 pad)
#define SMEM_FLOATS 21564
#define SMEM_BYTES  (SMEM_FLOATS * 4)   // 86256

__device__ __forceinline__ ull ffma2(ull a, ull b, ull c) {
    ull d; asm("fma.rn.f32x2 %0,%1,%2,%3;" : "=l"(d) : "l"(a), "l"(b), "l"(c)); return d;
}
__device__ __forceinline__ ull pack2(float lo, float hi) {
    ull d; asm("mov.b64 %0,{%1,%2};" : "=l"(d) : "f"(lo), "f"(hi)); return d;
}
__device__ __forceinline__ void unpack2(ull v, float& lo, float& hi) {
    asm("mov.b64 {%0,%1},%2;" : "=f"(lo), "=f"(hi) : "l"(v));
}
__device__ __forceinline__ float lrelu(float v) { return fmaxf(v, 0.2f * v); }

// conv1 quarter: ONE input channel, all 9 taps, 2 oc-pair accumulators.
// Weight per (c,k) tap = 1 ulonglong2 (4 oc), loaded once, reused ~5.4 positions.
__device__ __forceinline__ void conv_cq(const float* __restrict__ wb,
                                        const ull (&fp)[9], ull (&o2)[2][9]) {
#pragma unroll
    for (int k = 0; k < 9; ++k) {
        const int ky = k / 3, kx = k % 3;
        ulonglong2 w = *reinterpret_cast<const ulonglong2*>(wb + k * 4);
#pragma unroll
        for (int y = 0; y < 3; ++y) {
            const int iy = y + ky - 1;
            if (iy < 0 || iy > 2) continue;
#pragma unroll
            for (int x = 0; x < 3; ++x) {
                const int ix = x + kx - 1;
                if (ix < 0 || ix > 2) continue;
                const int q = y * 3 + x, p = iy * 3 + ix;
                o2[0][q] = ffma2(w.x, fp[p], o2[0][q]);
                o2[1][q] = ffma2(w.y, fp[p], o2[1][q]);
            }
        }
    }
}

// lrelu + 2x2/s1 maxpool + conv2 accumulate for one conv1 channel (W2 in smem)
__device__ __forceinline__ void poolc2(const float* __restrict__ sm,
                                       float r0, float r1, float r2,
                                       float r3, float r4, float r5,
                                       float r6, float r7, float r8,
                                       int oc, ull (&aa)[16])
{
    r0 = lrelu(r0); r1 = lrelu(r1); r2 = lrelu(r2);
    r3 = lrelu(r3); r4 = lrelu(r4); r5 = lrelu(r5);
    r6 = lrelu(r6); r7 = lrelu(r7); r8 = lrelu(r8);
    float p0 = fmaxf(fmaxf(r0, r1), fmaxf(r3, r4));
    float p1 = fmaxf(fmaxf(r1, r2), fmaxf(r4, r5));
    float p2 = fmaxf(fmaxf(r3, r4), fmaxf(r6, r7));
    float p3 = fmaxf(fmaxf(r4, r5), fmaxf(r7, r8));
#pragma unroll
    for (int q = 0; q < 4; ++q) {
        float pv = (q == 0) ? p0 : (q == 1) ? p1 : (q == 2) ? p2 : p3;
        ull pq = pack2(pv, pv);
        const ulonglong2* wp = reinterpret_cast<const ulonglong2*>(
            sm + W2_OFF + (oc * 4 + q) * 32);
#pragma unroll
        for (int g = 0; g < 8; ++g) {
            ulonglong2 w = wp[g];
            aa[2 * g]     = ffma2(w.x, pq, aa[2 * g]);
            aa[2 * g + 1] = ffma2(w.y, pq, aa[2 * g + 1]);
        }
    }
}

__global__ void __launch_bounds__(TPB, 2)
disc_kernel(const int* __restrict__ state, const int* __restrict__ des,
            const int* __restrict__ act,
            const int* __restrict__ asp, const int* __restrict__ pm,
            const float* __restrict__ path_feature,
            const float* __restrict__ link_feature,
            const float* __restrict__ c1w, const float* __restrict__ c1b,
            const float* __restrict__ c2w, const float* __restrict__ c2b,
            const float* __restrict__ f1w, const float* __restrict__ f1b,
            const float* __restrict__ f2w, const float* __restrict__ f2b,
            const float* __restrict__ f3w, const float* __restrict__ f3b,
            float* __restrict__ out, int B)
{
    extern __shared__ float sm[];
    const int tid = threadIdx.x;

    // ---------- stage + repack weights ----------
    for (int i = tid; i < 3780; i += TPB) {            // W1 [pass][c][k][4oc]
        int pass = i / 756; int r = i % 756;
        int c = r / 36; int r2 = r % 36;
        int k = r2 / 4; int j = r2 % 4;
        sm[W1_OFF + i] = c1w[((pass * 4 + j) * 21 + c) * 9 + k];
    }
    for (int i = tid; i < 2560; i += TPB) {            // W2 [oc][q][32pad]
        int oc = i / 128; int rem = i % 128; int q = rem / 32; int oc2 = rem % 32;
        sm[W2_OFF + i] = (oc2 < 30) ? c2w[(oc2 * 20 + oc) * 4 + q] : 0.f;
    }
    for (int i = tid; i < 3840; i += TPB) {            // FC1 [j1][32]
        int j = i / 32; int k = i % 32;
        sm[FC1P_OFF + i] = (k < 30) ? f1w[j * 38 + k] : 0.f;
    }
    for (int i = tid; i < 960; i += TPB) {             // FC1 one-hot cols
        int j = i / 8; int a8 = i % 8;
        sm[FC1OH_OFF + i] = f1w[j * 38 + 30 + a8];
    }
    for (int i = tid; i < 10080; i += TPB) {           // FC2 transposed [j1][84]
        int j1 = i / 84; int j2 = i % 84;
        sm[FC2T_OFF + i] = f2w[j2 * 120 + j1];
    }
    for (int i = tid; i < 84; i += TPB) sm[FC3_OFF + i] = f3w[i];
    if (tid < 20) sm[B1_OFF + tid] = c1b[tid];
    if (tid < 32) sm[B2P_OFF + tid] = (tid < 30) ? c2b[tid] : 0.f;
    if (tid < 120) sm[FB1_OFF + tid] = f1b[tid];
    if (tid < 84) sm[FB2_OFF + tid] = f2b[tid];
    if (tid == 0) sm[FB3_OFF] = f3b[0];
    __syncthreads();

    const int b = blockIdx.x * TPB + tid;
    if (b >= B) return;

    const int s = state[b];
    const int a = act[b];
    const float* pbase = path_feature + (size_t)des[b] * 12;  // row(n) = pbase + n*3600
    const int* pmrow = pm + s * 9;

    // position p uses neighbor NEW_INDEX[p]
    const int NI[9] = {7, 0, 1, 6, 8, 2, 5, 4, 3};
    int nnp[9];
#pragma unroll
    for (int p = 0; p < 9; ++p) nnp[p] = asp[s * 9 + NI[p]];

    ull aa[16];
#pragma unroll
    for (int j = 0; j < 16; ++j)
        aa[j] = pack2(sm[B2P_OFF + 2 * j], sm[B2P_OFF + 2 * j + 1]);

    // ---------- conv1 in 5 quarter-passes of 4 oc, fused pool+conv2 ----------
#pragma unroll 1
    for (int pass = 0; pass < 5; ++pass) {
        const float* wbP = sm + W1_OFF + pass * 756;
        ull o2[2][9];
        {
            ull b0 = pack2(sm[B1_OFF + 4 * pass],     sm[B1_OFF + 4 * pass + 1]);
            ull b1 = pack2(sm[B1_OFF + 4 * pass + 2], sm[B1_OFF + 4 * pass + 3]);
#pragma unroll
            for (int q = 0; q < 9; ++q) { o2[0][q] = b0; o2[1][q] = b1; }
        }
        // path channels 0..11
#pragma unroll 1
        for (int c = 0; c < 12; ++c) {
            ull fp[9];
#pragma unroll
            for (int p = 0; p < 9; ++p) {
                float fv = pbase[(size_t)nnp[p] * 3600 + c];
                fp[p] = pack2(fv, fv);
            }
            conv_cq(wbP + c * 36, fp, o2);
        }
        // link channels 12..19
#pragma unroll 1
        for (int c = 0; c < 8; ++c) {
            ull fp[9];
#pragma unroll
            for (int p = 0; p < 9; ++p) {
                float fv = link_feature[(size_t)nnp[p] * 8 + c];
                fp[p] = pack2(fv, fv);
            }
            conv_cq(wbP + (12 + c) * 36, fp, o2);
        }
        // mask channel 20
        {
            ull fp[9];
#pragma unroll
            for (int p = 0; p < 9; ++p) {
                float mv = (float)pmrow[NI[p]];
                fp[p] = pack2(mv, mv);
            }
            conv_cq(wbP + 20 * 36, fp, o2);
        }
        // drain: lrelu + pool + conv2 for oc 4*pass .. 4*pass+3
#pragma unroll
        for (int u = 0; u < 2; ++u) {
            float l0,h0,l1,h1,l2,h2,l3,h3,l4,h4,l5,h5,l6,h6,l7,h7,l8,h8;
            unpack2(o2[u][0], l0, h0); unpack2(o2[u][1], l1, h1); unpack2(o2[u][2], l2, h2);
            unpack2(o2[u][3], l3, h3); unpack2(o2[u][4], l4, h4); unpack2(o2[u][5], l5, h5);
            unpack2(o2[u][6], l6, h6); unpack2(o2[u][7], l7, h7); unpack2(o2[u][8], l8, h8);
            poolc2(sm, l0,l1,l2,l3,l4,l5,l6,l7,l8, 4 * pass + 2 * u,     aa);
            poolc2(sm, h0,h1,h2,h3,h4,h5,h6,h7,h8, 4 * pass + 2 * u + 1, aa);
        }
    }

    // ---------- fc input ----------
    ull x2[16];
#pragma unroll
    for (int j = 0; j < 15; ++j) {
        float lo, hi; unpack2(aa[j], lo, hi);
        x2[j] = pack2(lrelu(lo), lrelu(hi));
    }
    x2[15] = pack2(0.f, 0.f);

    float zacc = 0.f;

    // fc1 (recomputed per half) + fc2 half + fc3 partial.
    // Half A: j2 0..43 (hh[22], fc2 ul2 g=0..10); Half B: j2 44..83 (hh[20], g=11..20).
#define FC_HALF(NH, GBASE, JBASE) { \
    ull hh[NH]; \
    _Pragma("unroll") \
    for (int j = 0; j < (NH); ++j) \
        hh[j] = pack2(sm[FB2_OFF + 2 * ((JBASE) + j)], sm[FB2_OFF + 2 * ((JBASE) + j) + 1]); \
    _Pragma("unroll 2") \
    for (int j1 = 0; j1 < 120; ++j1) { \
        const ulonglong2* wp = reinterpret_cast<const ulonglong2*>(sm + FC1P_OFF + j1 * 32); \
        ull t0 = 0ull, t1 = 0ull, t2 = 0ull, t3 = 0ull; \
        _Pragma("unroll") \
        for (int g = 0; g < 4; ++g) { \
            ulonglong2 wA = wp[2 * g], wB = wp[2 * g + 1]; \
            t0 = ffma2(wA.x, x2[4 * g],     t0); \
            t1 = ffma2(wA.y, x2[4 * g + 1], t1); \
            t2 = ffma2(wB.x, x2[4 * g + 2], t2); \
            t3 = ffma2(wB.y, x2[4 * g + 3], t3); \
        } \
        float s0, s1, s2, s3, s4, s5, s6, s7; \
        unpack2(t0, s0, s1); unpack2(t1, s2, s3); unpack2(t2, s4, s5); unpack2(t3, s6, s7); \
        float t = sm[FB1_OFF + j1] + sm[FC1OH_OFF + j1 * 8 + a] \
                + (((s0 + s1) + (s2 + s3)) + ((s4 + s5) + (s6 + s7))); \
        t = lrelu(t); \
        ull tt = pack2(t, t); \
        const ulonglong2* w2p = reinterpret_cast<const ulonglong2*>(sm + FC2T_OFF + j1 * 84); \
        _Pragma("unroll") \
        for (int g = 0; g < (NH) / 2; ++g) { \
            ulonglong2 w = w2p[(GBASE) + g]; \
            hh[2 * g]     = ffma2(w.x, tt, hh[2 * g]); \
            hh[2 * g + 1] = ffma2(w.y, tt, hh[2 * g + 1]); \
        } \
    } \
    float z0 = 0.f, z1 = 0.f, z2 = 0.f, z3 = 0.f; \
    _Pragma("unroll") \
    for (int j = 0; j < (NH); ++j) { \
        float lo, hi; unpack2(hh[j], lo, hi); \
        lo = lrelu(lo); hi = lrelu(hi); \
        if (j & 1) { z2 += lo * sm[FC3_OFF + 2 * ((JBASE) + j)]; \
                     z3 += hi * sm[FC3_OFF + 2 * ((JBASE) + j) + 1]; } \
        else       { z0 += lo * sm[FC3_OFF + 2 * ((JBASE) + j)]; \
                     z1 += hi * sm[FC3_OFF + 2 * ((JBASE) + j) + 1]; } \
    } \
    zacc += ((z0 + z1) + (z2 + z3)); }

    FC_HALF(22, 0,  0)
    FC_HALF(20, 11, 22)
#undef FC_HALF

    float z = sm[FB3_OFF] + zacc;
    out[b] = 1.f / (1.f + expf(-z));
}

extern "C" void kernel_launch(void* const* d_in, const int* in_sizes, int n_in,
                              void* d_out, int out_size)
{
    const int*   state = (const int*)d_in[0];
    const int*   des   = (const int*)d_in[1];
    const int*   act   = (const int*)d_in[2];
    const int*   asp   = (const int*)d_in[3];
    const int*   pm    = (const int*)d_in[4];
    const float* pf    = (const float*)d_in[5];
    const float* lf    = (const float*)d_in[6];
    const float* c1w   = (const float*)d_in[7];
    const float* c1b   = (const float*)d_in[8];
    const float* c2w   = (const float*)d_in[9];
    const float* c2b   = (const float*)d_in[10];
    const float* f1w   = (const float*)d_in[11];
    const float* f1b   = (const float*)d_in[12];
    const float* f2w   = (const float*)d_in[13];
    const float* f2b   = (const float*)d_in[14];
    const float* f3w   = (const float*)d_in[15];
    const float* f3b   = (const float*)d_in[16];

    const int B = in_sizes[0];
    float* out = (float*)d_out;

    cudaFuncSetAttribute(disc_kernel, cudaFuncAttributeMaxDynamicSharedMemorySize, SMEM_BYTES);

    const int grid = (B + TPB - 1) / TPB;
    disc_kernel<<<grid, TPB, SMEM_BYTES>>>(state, des, act, asp, pm, pf, lf,
                                           c1w, c1b, c2w, c2b,
                                           f1w, f1b, f2w, f2b, f3w, f3b,
                                           out, B);
}

// round 13
// speedup vs baseline: 1.5989x; 1.5989x over previous
#include <cuda_runtime.h>
#include <math.h>

typedef unsigned long long ull;

#define TPB 256

// ---- shared memory float offsets (89280 B -> 2 blocks/SM, 16 warps/SM) ----
#define W1_OFF    0        // conv1 [half][c][k][12] : 2*21*9*12 = 4536
#define W2_OFF    4536     // conv2 [oc][q][32pad]   : 20*4*32  = 2560
#define FC1P_OFF  7096     // fc1 [j1][32] (cols 0..29, pad 0) : 3840
#define FC1OH_OFF 10936    // fc1 one-hot cols [j1][8] : 960
#define FC2T_OFF  11896    // fc2 transposed [j1][84] : 10080
#define FC3_OFF   21976    // 84
#define B1_OFF    22060    // 20
#define B2P_OFF   22080    // 32
#define FB1_OFF   22112    // 120
#define FB2_OFF   22232    // 84
#define FB3_OFF   22316    // 1 (+3 pad)
#define SMEM_FLOATS 22320
#define SMEM_BYTES  (SMEM_FLOATS * 4)

__device__ __forceinline__ ull ffma2(ull a, ull b, ull c) {
    ull d; asm("fma.rn.f32x2 %0,%1,%2,%3;" : "=l"(d) : "l"(a), "l"(b), "l"(c)); return d;
}
__device__ __forceinline__ ull pack2(float lo, float hi) {
    ull d; asm("mov.b64 %0,{%1,%2};" : "=l"(d) : "f"(lo), "f"(hi)); return d;
}
__device__ __forceinline__ void unpack2(ull v, float& lo, float& hi) {
    asm("mov.b64 {%0,%1},%2;" : "=f"(lo), "=f"(hi) : "l"(v));
}
__device__ __forceinline__ float lrelu(float v) { return fmaxf(v, 0.2f * v); }

// conv1, ONE input channel, all 9 taps, 10 oc (5 fp32x2 pairs). Weight per
// (c,k) loaded once and reused across all valid output positions.
__device__ __forceinline__ void conv_c(const float* __restrict__ wb,
                                       const ull (&fp)[9], ull (&o2)[5][9]) {
#pragma unroll
    for (int k = 0; k < 9; ++k) {
        const int ky = k / 3, kx = k % 3;
        const float* wr = wb + k * 12;
        ulonglong2 wa = *reinterpret_cast<const ulonglong2*>(wr);
        ulonglong2 wv = *reinterpret_cast<const ulonglong2*>(wr + 4);
        ull wc = *reinterpret_cast<const ull*>(wr + 8);
#pragma unroll
        for (int y = 0; y < 3; ++y) {
            const int iy = y + ky - 1;
            if (iy < 0 || iy > 2) continue;
#pragma unroll
            for (int x = 0; x < 3; ++x) {
                const int ix = x + kx - 1;
                if (ix < 0 || ix > 2) continue;
                const int q = y * 3 + x, p = iy * 3 + ix;
                o2[0][q] = ffma2(wa.x, fp[p], o2[0][q]);
                o2[1][q] = ffma2(wa.y, fp[p], o2[1][q]);
                o2[2][q] = ffma2(wv.x, fp[p], o2[2][q]);
                o2[3][q] = ffma2(wv.y, fp[p], o2[3][q]);
                o2[4][q] = ffma2(wc,   fp[p], o2[4][q]);
            }
        }
    }
}

// lrelu + 2x2/s1 maxpool + conv2 accumulate for one conv1 channel (W2 in smem)
__device__ __forceinline__ void poolc2(const float* __restrict__ sm,
                                       float r0, float r1, float r2,
                                       float r3, float r4, float r5,
                                       float r6, float r7, float r8,
                                       int oc, ull (&aa)[16])
{
    r0 = lrelu(r0); r1 = lrelu(r1); r2 = lrelu(r2);
    r3 = lrelu(r3); r4 = lrelu(r4); r5 = lrelu(r5);
    r6 = lrelu(r6); r7 = lrelu(r7); r8 = lrelu(r8);
    float p0 = fmaxf(fmaxf(r0, r1), fmaxf(r3, r4));
    float p1 = fmaxf(fmaxf(r1, r2), fmaxf(r4, r5));
    float p2 = fmaxf(fmaxf(r3, r4), fmaxf(r6, r7));
    float p3 = fmaxf(fmaxf(r4, r5), fmaxf(r7, r8));
#pragma unroll
    for (int q = 0; q < 4; ++q) {
        float pv = (q == 0) ? p0 : (q == 1) ? p1 : (q == 2) ? p2 : p3;
        ull pq = pack2(pv, pv);
        const ulonglong2* wp = reinterpret_cast<const ulonglong2*>(
            sm + W2_OFF + (oc * 4 + q) * 32);
#pragma unroll
        for (int g = 0; g < 8; ++g) {
            ulonglong2 w = wp[g];
            aa[2 * g]     = ffma2(w.x, pq, aa[2 * g]);
            aa[2 * g + 1] = ffma2(w.y, pq, aa[2 * g + 1]);
        }
    }
}

__global__ void __launch_bounds__(TPB, 2)
disc_kernel(const int* __restrict__ state, const int* __restrict__ des,
            const int* __restrict__ act,
            const int* __restrict__ asp, const int* __restrict__ pm,
            const float* __restrict__ path_feature,
            const float* __restrict__ link_feature,
            const float* __restrict__ c1w, const float* __restrict__ c1b,
            const float* __restrict__ c2w, const float* __restrict__ c2b,
            const float* __restrict__ f1w, const float* __restrict__ f1b,
            const float* __restrict__ f2w, const float* __restrict__ f2b,
            const float* __restrict__ f3w, const float* __restrict__ f3b,
            float* __restrict__ out, int B)
{
    extern __shared__ float sm[];
    const int tid = threadIdx.x;

    // ---------- stage + repack weights ----------
    for (int i = tid; i < 4536; i += TPB) {            // W1 [half][c][k][12]
        int half = i / 2268; int r = i % 2268;
        int c = r / 108; int r2 = r % 108;
        int k = r2 / 12; int j = r2 % 12;
        sm[W1_OFF + i] = (j < 10) ? c1w[((half * 10 + j) * 21 + c) * 9 + k] : 0.f;
    }
    for (int i = tid; i < 2560; i += TPB) {            // W2 [oc][q][32pad]
        int oc = i / 128; int rem = i % 128; int q = rem / 32; int oc2 = rem % 32;
        sm[W2_OFF + i] = (oc2 < 30) ? c2w[(oc2 * 20 + oc) * 4 + q] : 0.f;
    }
    for (int i = tid; i < 3840; i += TPB) {            // FC1 [j1][32]
        int j = i / 32; int k = i % 32;
        sm[FC1P_OFF + i] = (k < 30) ? f1w[j * 38 + k] : 0.f;
    }
    for (int i = tid; i < 960; i += TPB) {             // FC1 one-hot cols
        int j = i / 8; int a8 = i % 8;
        sm[FC1OH_OFF + i] = f1w[j * 38 + 30 + a8];
    }
    for (int i = tid; i < 10080; i += TPB) {           // FC2 transposed [j1][84]
        int j1 = i / 84; int j2 = i % 84;
        sm[FC2T_OFF + i] = f2w[j2 * 120 + j1];
    }
    for (int i = tid; i < 84; i += TPB) sm[FC3_OFF + i] = f3w[i];
    if (tid < 20) sm[B1_OFF + tid] = c1b[tid];
    if (tid < 32) sm[B2P_OFF + tid] = (tid < 30) ? c2b[tid] : 0.f;
    if (tid < 120) sm[FB1_OFF + tid] = f1b[tid];
    if (tid < 84) sm[FB2_OFF + tid] = f2b[tid];
    if (tid == 0) sm[FB3_OFF] = f3b[0];
    __syncthreads();

    const int b = blockIdx.x * TPB + tid;
    if (b >= B) return;

    const int s = state[b];
    const int a = act[b];
    const float* pbase = path_feature + (size_t)des[b] * 12;  // row(n) = pbase + n*3600
    const int* pmrow = pm + s * 9;

    // position p uses neighbor NEW_INDEX[p]
    const int NI[9] = {7, 0, 1, 6, 8, 2, 5, 4, 3};
    int nnp[9];
#pragma unroll
    for (int p = 0; p < 9; ++p) nnp[p] = asp[s * 9 + NI[p]];

    ull o2[5][9];
    ull aa[16];

    // one conv half: scalar feature loads per channel, weights reused per (c,k)
#define HALF_CONV(H) { \
    const float* wbH = sm + W1_OFF + (H) * 2268; \
    _Pragma("unroll 1") \
    for (int c = 0; c < 12; ++c) {        /* path channels */ \
        ull fp[9]; \
        _Pragma("unroll") \
        for (int p = 0; p < 9; ++p) { \
            float fv = pbase[(size_t)nnp[p] * 3600 + c]; \
            fp[p] = pack2(fv, fv); \
        } \
        conv_c(wbH + c * 108, fp, o2); \
    } \
    _Pragma("unroll 1") \
    for (int c = 0; c < 8; ++c) {         /* link channels */ \
        ull fp[9]; \
        _Pragma("unroll") \
        for (int p = 0; p < 9; ++p) { \
            float fv = link_feature[(size_t)nnp[p] * 8 + c]; \
            fp[p] = pack2(fv, fv); \
        } \
        conv_c(wbH + (12 + c) * 108, fp, o2); \
    } \
    {                                     /* mask channel */ \
        ull fp[9]; \
        _Pragma("unroll") \
        for (int p = 0; p < 9; ++p) { \
            float mv = (float)pmrow[NI[p]]; \
            fp[p] = pack2(mv, mv); \
        } \
        conv_c(wbH + 20 * 108, fp, o2); \
    } }

#define POOLHALF(OCBASE) { \
    _Pragma("unroll") \
    for (int u = 0; u < 5; ++u) { \
        float l0,h0,l1,h1,l2,h2,l3,h3,l4,h4,l5,h5,l6,h6,l7,h7,l8,h8; \
        unpack2(o2[u][0], l0, h0); unpack2(o2[u][1], l1, h1); unpack2(o2[u][2], l2, h2); \
        unpack2(o2[u][3], l3, h3); unpack2(o2[u][4], l4, h4); unpack2(o2[u][5], l5, h5); \
        unpack2(o2[u][6], l6, h6); unpack2(o2[u][7], l7, h7); unpack2(o2[u][8], l8, h8); \
        poolc2(sm, l0,l1,l2,l3,l4,l5,l6,l7,l8, (OCBASE) + 2*u,     aa); \
        poolc2(sm, h0,h1,h2,h3,h4,h5,h6,h7,h8, (OCBASE) + 2*u + 1, aa); } }

    // ---------- half 0 : oc 0..9 ----------
#pragma unroll
    for (int u = 0; u < 5; ++u) {
        ull bb = pack2(sm[B1_OFF + 2 * u], sm[B1_OFF + 2 * u + 1]);
#pragma unroll
        for (int q = 0; q < 9; ++q) o2[u][q] = bb;
    }
    HALF_CONV(0);
#pragma unroll
    for (int j = 0; j < 16; ++j)
        aa[j] = pack2(sm[B2P_OFF + 2 * j], sm[B2P_OFF + 2 * j + 1]);
    POOLHALF(0);

    // ---------- half 1 : oc 10..19 (re-gather, L2 hits) ----------
#pragma unroll
    for (int u = 0; u < 5; ++u) {
        ull bb = pack2(sm[B1_OFF + 10 + 2 * u], sm[B1_OFF + 11 + 2 * u]);
#pragma unroll
        for (int q = 0; q < 9; ++q) o2[u][q] = bb;
    }
    HALF_CONV(1);
    POOLHALF(10);

#undef HALF_CONV
#undef POOLHALF

    // ---------- fc input ----------
    ull x2[16];
#pragma unroll
    for (int j = 0; j < 15; ++j) {
        float lo, hi; unpack2(aa[j], lo, hi);
        x2[j] = pack2(lrelu(lo), lrelu(hi));
    }
    x2[15] = pack2(0.f, 0.f);

    float zacc = 0.f;

    // fc1 (recomputed per half) + fc2 half + fc3 partial.
    // Half A: j2 0..43 (hh[22], fc2 ul2 g=0..10); Half B: j2 44..83 (hh[20], g=11..20).
#define FC_HALF(NH, GBASE, JBASE) { \
    ull hh[NH]; \
    _Pragma("unroll") \
    for (int j = 0; j < (NH); ++j) \
        hh[j] = pack2(sm[FB2_OFF + 2 * ((JBASE) + j)], sm[FB2_OFF + 2 * ((JBASE) + j) + 1]); \
    _Pragma("unroll 2") \
    for (int j1 = 0; j1 < 120; ++j1) { \
        const ulonglong2* wp = reinterpret_cast<const ulonglong2*>(sm + FC1P_OFF + j1 * 32); \
        ull t0 = 0ull, t1 = 0ull, t2 = 0ull, t3 = 0ull; \
        _Pragma("unroll") \
        for (int g = 0; g < 4; ++g) { \
            ulonglong2 wA = wp[2 * g], wB = wp[2 * g + 1]; \
            t0 = ffma2(wA.x, x2[4 * g],     t0); \
            t1 = ffma2(wA.y, x2[4 * g + 1], t1); \
            t2 = ffma2(wB.x, x2[4 * g + 2], t2); \
            t3 = ffma2(wB.y, x2[4 * g + 3], t3); \
        } \
        float s0, s1, s2, s3, s4, s5, s6, s7; \
        unpack2(t0, s0, s1); unpack2(t1, s2, s3); unpack2(t2, s4, s5); unpack2(t3, s6, s7); \
        float t = sm[FB1_OFF + j1] + sm[FC1OH_OFF + j1 * 8 + a] \
                + (((s0 + s1) + (s2 + s3)) + ((s4 + s5) + (s6 + s7))); \
        t = lrelu(t); \
        ull tt = pack2(t, t); \
        const ulonglong2* w2p = reinterpret_cast<const ulonglong2*>(sm + FC2T_OFF + j1 * 84); \
        _Pragma("unroll") \
        for (int g = 0; g < (NH) / 2; ++g) { \
            ulonglong2 w = w2p[(GBASE) + g]; \
            hh[2 * g]     = ffma2(w.x, tt, hh[2 * g]); \
            hh[2 * g + 1] = ffma2(w.y, tt, hh[2 * g + 1]); \
        } \
    } \
    float z0 = 0.f, z1 = 0.f, z2 = 0.f, z3 = 0.f; \
    _Pragma("unroll") \
    for (int j = 0; j < (NH); ++j) { \
        float lo, hi; unpack2(hh[j], lo, hi); \
        lo = lrelu(lo); hi = lrelu(hi); \
        if (j & 1) { z2 += lo * sm[FC3_OFF + 2 * ((JBASE) + j)]; \
                     z3 += hi * sm[FC3_OFF + 2 * ((JBASE) + j) + 1]; } \
        else       { z0 += lo * sm[FC3_OFF + 2 * ((JBASE) + j)]; \
                     z1 += hi * sm[FC3_OFF + 2 * ((JBASE) + j) + 1]; } \
    } \
    zacc += ((z0 + z1) + (z2 + z3)); }

    FC_HALF(22, 0,  0)
    FC_HALF(20, 11, 22)
#undef FC_HALF

    float z = sm[FB3_OFF] + zacc;
    out[b] = 1.f / (1.f + expf(-z));
}

extern "C" void kernel_launch(void* const* d_in, const int* in_sizes, int n_in,
                              void* d_out, int out_size)
{
    const int*   state = (const int*)d_in[0];
    const int*   des   = (const int*)d_in[1];
    const int*   act   = (const int*)d_in[2];
    const int*   asp   = (const int*)d_in[3];
    const int*   pm    = (const int*)d_in[4];
    const float* pf    = (const float*)d_in[5];
    const float* lf    = (const float*)d_in[6];
    const float* c1w   = (const float*)d_in[7];
    const float* c1b   = (const float*)d_in[8];
    const float* c2w   = (const float*)d_in[9];
    const float* c2b   = (const float*)d_in[10];
    const float* f1w   = (const float*)d_in[11];
    const float* f1b   = (const float*)d_in[12];
    const float* f2w   = (const float*)d_in[13];
    const float* f2b   = (const float*)d_in[14];
    const float* f3w   = (const float*)d_in[15];
    const float* f3b   = (const float*)d_in[16];

    const int B = in_sizes[0];
    float* out = (float*)d_out;

    cudaFuncSetAttribute(disc_kernel, cudaFuncAttributeMaxDynamicSharedMemorySize, SMEM_BYTES);

    const int grid = (B + TPB - 1) / TPB;
    disc_kernel<<<grid, TPB, SMEM_BYTES>>>(state, des, act, asp, pm, pf, lf,
                                           c1w, c1b, c2w, c2b,
                                           f1w, f1b, f2w, f2b, f3w, f3b,
                                           out, B);
}

// round 14
// speedup vs baseline: 2.3870x; 1.4928x over previous
#include <cuda_runtime.h>
#include <math.h>

typedef unsigned long long ull;

#define TPB 224

// ---- shared memory float offsets (89280 B -> 2 blocks/SM, 14 warps/SM) ----
#define W1_OFF    0        // conv1 [half][c][k][12] : 2*21*9*12 = 4536
#define W2_OFF    4536     // conv2 [oc][q][32pad]   : 20*4*32  = 2560
#define FC1P_OFF  7096     // fc1 [j1][32] (cols 0..29, pad 0) : 3840
#define FC1OH_OFF 10936    // fc1 one-hot cols [j1][8] : 960
#define FC2T_OFF  11896    // fc2 transposed [j1][84] : 10080
#define FC3_OFF   21976    // 84
#define B1_OFF    22060    // 20
#define B2P_OFF   22080    // 32
#define FB1_OFF   22112    // 120
#define FB2_OFF   22232    // 84
#define FB3_OFF   22316    // 1 (+3 pad)
#define SMEM_FLOATS 22320
#define SMEM_BYTES  (SMEM_FLOATS * 4)

__device__ __forceinline__ ull ffma2(ull a, ull b, ull c) {
    ull d; asm("fma.rn.f32x2 %0,%1,%2,%3;" : "=l"(d) : "l"(a), "l"(b), "l"(c)); return d;
}
__device__ __forceinline__ ull pack2(float lo, float hi) {
    ull d; asm("mov.b64 %0,{%1,%2};" : "=l"(d) : "f"(lo), "f"(hi)); return d;
}
__device__ __forceinline__ void unpack2(ull v, float& lo, float& hi) {
    asm("mov.b64 {%0,%1},%2;" : "=f"(lo), "=f"(hi) : "l"(v));
}
__device__ __forceinline__ float lrelu(float v) { return fmaxf(v, 0.2f * v); }

// conv1, ONE input channel, all 9 taps, weights loaded once per tap and
// reused across every valid output position. (identical to R10)
__device__ __forceinline__ void conv_c(const float* __restrict__ wb,
                                       const ull (&fp)[9], ull (&o2)[5][9]) {
#pragma unroll
    for (int k = 0; k < 9; ++k) {
        const int ky = k / 3, kx = k % 3;
        const float* wr = wb + k * 12;
        ulonglong2 wa = *reinterpret_cast<const ulonglong2*>(wr);
        ulonglong2 wv = *reinterpret_cast<const ulonglong2*>(wr + 4);
        ull wc = *reinterpret_cast<const ull*>(wr + 8);
#pragma unroll
        for (int y = 0; y < 3; ++y) {
            const int iy = y + ky - 1;
            if (iy < 0 || iy > 2) continue;
#pragma unroll
            for (int x = 0; x < 3; ++x) {
                const int ix = x + kx - 1;
                if (ix < 0 || ix > 2) continue;
                const int q = y * 3 + x, p = iy * 3 + ix;
                o2[0][q] = ffma2(wa.x, fp[p], o2[0][q]);
                o2[1][q] = ffma2(wa.y, fp[p], o2[1][q]);
                o2[2][q] = ffma2(wv.x, fp[p], o2[2][q]);
                o2[3][q] = ffma2(wv.y, fp[p], o2[3][q]);
                o2[4][q] = ffma2(wc,   fp[p], o2[4][q]);
            }
        }
    }
}

// lrelu + 2x2/s1 maxpool + conv2 accumulate for one conv1 channel (W2 in smem)
__device__ __forceinline__ void poolc2(const float* __restrict__ sm,
                                       float r0, float r1, float r2,
                                       float r3, float r4, float r5,
                                       float r6, float r7, float r8,
                                       int oc, ull (&aa)[16])
{
    r0 = lrelu(r0); r1 = lrelu(r1); r2 = lrelu(r2);
    r3 = lrelu(r3); r4 = lrelu(r4); r5 = lrelu(r5);
    r6 = lrelu(r6); r7 = lrelu(r7); r8 = lrelu(r8);
    float p0 = fmaxf(fmaxf(r0, r1), fmaxf(r3, r4));
    float p1 = fmaxf(fmaxf(r1, r2), fmaxf(r4, r5));
    float p2 = fmaxf(fmaxf(r3, r4), fmaxf(r6, r7));
    float p3 = fmaxf(fmaxf(r4, r5), fmaxf(r7, r8));
#pragma unroll
    for (int q = 0; q < 4; ++q) {
        float pv = (q == 0) ? p0 : (q == 1) ? p1 : (q == 2) ? p2 : p3;
        ull pq = pack2(pv, pv);
        const ulonglong2* wp = reinterpret_cast<const ulonglong2*>(
            sm + W2_OFF + (oc * 4 + q) * 32);
#pragma unroll
        for (int g = 0; g < 8; ++g) {
            ulonglong2 w = wp[g];
            aa[2 * g]     = ffma2(w.x, pq, aa[2 * g]);
            aa[2 * g + 1] = ffma2(w.y, pq, aa[2 * g + 1]);
        }
    }
}

__global__ void __launch_bounds__(TPB, 2)
disc_kernel(const int* __restrict__ state, const int* __restrict__ des,
            const int* __restrict__ act,
            const int* __restrict__ asp, const int* __restrict__ pm,
            const float* __restrict__ path_feature,
            const float* __restrict__ link_feature,
            const float* __restrict__ c1w, const float* __restrict__ c1b,
            const float* __restrict__ c2w, const float* __restrict__ c2b,
            const float* __restrict__ f1w, const float* __restrict__ f1b,
            const float* __restrict__ f2w, const float* __restrict__ f2b,
            const float* __restrict__ f3w, const float* __restrict__ f3b,
            float* __restrict__ out, int B)
{
    extern __shared__ float sm[];
    const int tid = threadIdx.x;

    // ---------- stage + repack weights ----------
    for (int i = tid; i < 4536; i += TPB) {            // W1 [half][c][k][12]
        int half = i / 2268; int r = i % 2268;
        int c = r / 108; int r2 = r % 108;
        int k = r2 / 12; int j = r2 % 12;
        sm[W1_OFF + i] = (j < 10) ? c1w[((half * 10 + j) * 21 + c) * 9 + k] : 0.f;
    }
    for (int i = tid; i < 2560; i += TPB) {            // W2 [oc][q][32pad]
        int oc = i / 128; int rem = i % 128; int q = rem / 32; int oc2 = rem % 32;
        sm[W2_OFF + i] = (oc2 < 30) ? c2w[(oc2 * 20 + oc) * 4 + q] : 0.f;
    }
    for (int i = tid; i < 3840; i += TPB) {            // FC1 [j1][32]
        int j = i / 32; int k = i % 32;
        sm[FC1P_OFF + i] = (k < 30) ? f1w[j * 38 + k] : 0.f;
    }
    for (int i = tid; i < 960; i += TPB) {             // FC1 one-hot cols
        int j = i / 8; int a8 = i % 8;
        sm[FC1OH_OFF + i] = f1w[j * 38 + 30 + a8];
    }
    for (int i = tid; i < 10080; i += TPB) {           // FC2 transposed [j1][84]
        int j1 = i / 84; int j2 = i % 84;
        sm[FC2T_OFF + i] = f2w[j2 * 120 + j1];
    }
    for (int i = tid; i < 84; i += TPB) sm[FC3_OFF + i] = f3w[i];
    if (tid < 20) sm[B1_OFF + tid] = c1b[tid];
    if (tid < 32) sm[B2P_OFF + tid] = (tid < 30) ? c2b[tid] : 0.f;
    if (tid < 120) sm[FB1_OFF + tid] = f1b[tid];
    if (tid < 84) sm[FB2_OFF + tid] = f2b[tid];
    if (tid == 0) sm[FB3_OFF] = f3b[0];
    __syncthreads();

    const int b = blockIdx.x * TPB + tid;
    if (b >= B) return;

    const int s = state[b];
    const int a = act[b];
    const float* pbase = path_feature + (size_t)des[b] * 12;  // row(n) = pbase + n*3600
    const int* pmrow = pm + s * 9;

    // position p uses neighbor NEW_INDEX[p]
    const int NI[9] = {7, 0, 1, 6, 8, 2, 5, 4, 3};
    int nnp[9];
#pragma unroll
    for (int p = 0; p < 9; ++p) nnp[p] = asp[s * 9 + NI[p]];

    ull o2[5][9];
    ull aa[16];

    // one conv half: duos of channels via float2 loads, weights reused per (c,k)
#define HALF_CONV(H) { \
    const float* wbH = sm + W1_OFF + (H) * 2268; \
    _Pragma("unroll 1") \
    for (int d = 0; d < 6; ++d) {      /* path channels 0..11 */ \
        float2 f2[9]; \
        _Pragma("unroll") \
        for (int p = 0; p < 9; ++p) \
            f2[p] = *reinterpret_cast<const float2*>( \
                pbase + (size_t)nnp[p] * 3600 + 2 * d); \
        ull fp[9]; \
        _Pragma("unroll") \
        for (int p = 0; p < 9; ++p) fp[p] = pack2(f2[p].x, f2[p].x); \
        conv_c(wbH + (2 * d) * 108, fp, o2); \
        _Pragma("unroll") \
        for (int p = 0; p < 9; ++p) fp[p] = pack2(f2[p].y, f2[p].y); \
        conv_c(wbH + (2 * d + 1) * 108, fp, o2); \
    } \
    _Pragma("unroll 1") \
    for (int d = 0; d < 4; ++d) {      /* link channels 12..19 */ \
        float2 f2[9]; \
        _Pragma("unroll") \
        for (int p = 0; p < 9; ++p) \
            f2[p] = *reinterpret_cast<const float2*>( \
                link_feature + (size_t)nnp[p] * 8 + 2 * d); \
        ull fp[9]; \
        _Pragma("unroll") \
        for (int p = 0; p < 9; ++p) fp[p] = pack2(f2[p].x, f2[p].x); \
        conv_c(wbH + (12 + 2 * d) * 108, fp, o2); \
        _Pragma("unroll") \
        for (int p = 0; p < 9; ++p) fp[p] = pack2(f2[p].y, f2[p].y); \
        conv_c(wbH + (12 + 2 * d + 1) * 108, fp, o2); \
    } \
    {                                   /* mask channel 20 */ \
        ull fp[9]; \
        _Pragma("unroll") \
        for (int p = 0; p < 9; ++p) { \
            float mv = (float)pmrow[NI[p]]; \
            fp[p] = pack2(mv, mv); \
        } \
        conv_c(wbH + 20 * 108, fp, o2); \
    } }

#define POOLHALF(OCBASE) { \
    _Pragma("unroll") \
    for (int u = 0; u < 5; ++u) { \
        float l0,h0,l1,h1,l2,h2,l3,h3,l4,h4,l5,h5,l6,h6,l7,h7,l8,h8; \
        unpack2(o2[u][0], l0, h0); unpack2(o2[u][1], l1, h1); unpack2(o2[u][2], l2, h2); \
        unpack2(o2[u][3], l3, h3); unpack2(o2[u][4], l4, h4); unpack2(o2[u][5], l5, h5); \
        unpack2(o2[u][6], l6, h6); unpack2(o2[u][7], l7, h7); unpack2(o2[u][8], l8, h8); \
        poolc2(sm, l0,l1,l2,l3,l4,l5,l6,l7,l8, (OCBASE) + 2*u,     aa); \
        poolc2(sm, h0,h1,h2,h3,h4,h5,h6,h7,h8, (OCBASE) + 2*u + 1, aa); } }

    // ---------- half 0 : oc 0..9 ----------
#pragma unroll
    for (int u = 0; u < 5; ++u) {
        ull bb = pack2(sm[B1_OFF + 2 * u], sm[B1_OFF + 2 * u + 1]);
#pragma unroll
        for (int q = 0; q < 9; ++q) o2[u][q] = bb;
    }
    HALF_CONV(0);
#pragma unroll
    for (int j = 0; j < 16; ++j)
        aa[j] = pack2(sm[B2P_OFF + 2 * j], sm[B2P_OFF + 2 * j + 1]);
    POOLHALF(0);

    // ---------- half 1 : oc 10..19 (re-gather, L1/L2 hits) ----------
#pragma unroll
    for (int u = 0; u < 5; ++u) {
        ull bb = pack2(sm[B1_OFF + 10 + 2 * u], sm[B1_OFF + 11 + 2 * u]);
#pragma unroll
        for (int q = 0; q < 9; ++q) o2[u][q] = bb;
    }
    HALF_CONV(1);
    POOLHALF(10);

#undef HALF_CONV
#undef POOLHALF

    // ---------- fc input ----------
    ull x2[16];
#pragma unroll
    for (int j = 0; j < 15; ++j) {
        float lo, hi; unpack2(aa[j], lo, hi);
        x2[j] = pack2(lrelu(lo), lrelu(hi));
    }
    x2[15] = pack2(0.f, 0.f);

    float zacc = 0.f;

    // fc1 (recomputed per half) + fc2 half + fc3 partial — lowers fc reg peak.
    // Half A: j2 0..43 (hh[22], fc2 ul2 g=0..10); Half B: j2 44..83 (hh[20], g=11..20).
#define FC_HALF(NH, GBASE, JBASE) { \
    ull hh[NH]; \
    _Pragma("unroll") \
    for (int j = 0; j < (NH); ++j) \
        hh[j] = pack2(sm[FB2_OFF + 2 * ((JBASE) + j)], sm[FB2_OFF + 2 * ((JBASE) + j) + 1]); \
    _Pragma("unroll 2") \
    for (int j1 = 0; j1 < 120; ++j1) { \
        const ulonglong2* wp = reinterpret_cast<const ulonglong2*>(sm + FC1P_OFF + j1 * 32); \
        ull t0 = 0ull, t1 = 0ull, t2 = 0ull, t3 = 0ull; \
        _Pragma("unroll") \
        for (int g = 0; g < 4; ++g) { \
            ulonglong2 wA = wp[2 * g], wB = wp[2 * g + 1]; \
            t0 = ffma2(wA.x, x2[4 * g],     t0); \
            t1 = ffma2(wA.y, x2[4 * g + 1], t1); \
            t2 = ffma2(wB.x, x2[4 * g + 2], t2); \
            t3 = ffma2(wB.y, x2[4 * g + 3], t3); \
        } \
        float s0, s1, s2, s3, s4, s5, s6, s7; \
        unpack2(t0, s0, s1); unpack2(t1, s2, s3); unpack2(t2, s4, s5); unpack2(t3, s6, s7); \
        float t = sm[FB1_OFF + j1] + sm[FC1OH_OFF + j1 * 8 + a] \
                + (((s0 + s1) + (s2 + s3)) + ((s4 + s5) + (s6 + s7))); \
        t = lrelu(t); \
        ull tt = pack2(t, t); \
        const ulonglong2* w2p = reinterpret_cast<const ulonglong2*>(sm + FC2T_OFF + j1 * 84); \
        _Pragma("unroll") \
        for (int g = 0; g < (NH) / 2; ++g) { \
            ulonglong2 w = w2p[(GBASE) + g]; \
            hh[2 * g]     = ffma2(w.x, tt, hh[2 * g]); \
            hh[2 * g + 1] = ffma2(w.y, tt, hh[2 * g + 1]); \
        } \
    } \
    float z0 = 0.f, z1 = 0.f, z2 = 0.f, z3 = 0.f; \
    _Pragma("unroll") \
    for (int j = 0; j < (NH); ++j) { \
        float lo, hi; unpack2(hh[j], lo, hi); \
        lo = lrelu(lo); hi = lrelu(hi); \
        if (j & 1) { z2 += lo * sm[FC3_OFF + 2 * ((JBASE) + j)]; \
                     z3 += hi * sm[FC3_OFF + 2 * ((JBASE) + j) + 1]; } \
        else       { z0 += lo * sm[FC3_OFF + 2 * ((JBASE) + j)]; \
                     z1 += hi * sm[FC3_OFF + 2 * ((JBASE) + j) + 1]; } \
    } \
    zacc += ((z0 + z1) + (z2 + z3)); }

    FC_HALF(22, 0,  0)
    FC_HALF(20, 11, 22)
#undef FC_HALF

    float z = sm[FB3_OFF] + zacc;
    out[b] = 1.f / (1.f + expf(-z));
}

extern "C" void kernel_launch(void* const* d_in, const int* in_sizes, int n_in,
                              void* d_out, int out_size)
{
    const int*   state = (const int*)d_in[0];
    const int*   des   = (const int*)d_in[1];
    const int*   act   = (const int*)d_in[2];
    const int*   asp   = (const int*)d_in[3];
    const int*   pm    = (const int*)d_in[4];
    const float* pf    = (const float*)d_in[5];
    const float* lf    = (const float*)d_in[6];
    const float* c1w   = (const float*)d_in[7];
    const float* c1b   = (const float*)d_in[8];
    const float* c2w   = (const float*)d_in[9];
    const float* c2b   = (const float*)d_in[10];
    const float* f1w   = (const float*)d_in[11];
    const float* f1b   = (const float*)d_in[12];
    const float* f2w   = (const float*)d_in[13];
    const float* f2b   = (const float*)d_in[14];
    const float* f3w   = (const float*)d_in[15];
    const float* f3b   = (const float*)d_in[16];

    const int B = in_sizes[0];
    float* out = (float*)d_out;

    cudaFuncSetAttribute(disc_kernel, cudaFuncAttributeMaxDynamicSharedMemorySize, SMEM_BYTES);

    const int grid = (B + TPB - 1) / TPB;   // 293 blocks -> single wave
    disc_kernel<<<grid, TPB, SMEM_BYTES>>>(state, des, act, asp, pm, pf, lf,
                                           c1w, c1b, c2w, c2b,
                                           f1w, f1b, f2w, f2b, f3w, f3b,
                                           out, B);
}